// round 16
// baseline (speedup 1.0000x reference)
#include <cuda_runtime.h>
#include <cuda_fp16.h>
#include <math.h>
#include <stdint.h>

// Problem constants
#define BB 4
#define NN 1024
#define DD 512
#define LL 6
#define HH 8
#define DHH 64
#define FFI 2048          // FF_INNER
#define NKEY 1025         // N + 1 (null key prepended)

typedef __half hlf;

// ---------------- static device scratch ----------------
__device__ float g_x  [BB*NN*DD];       // residual stream
__device__ float g_qkv[BB*NN*640];      // fused q|k|v GEMM output
__device__ float g_q  [BB*NN*DD];       // rotated+normalized q
__device__ float g_k  [BB*NKEY*DHH];
__device__ float g_v  [BB*NKEY*DHH];
__device__ float g_pr [BB*NN*DD];
__device__ float g_bias[HH*NKEY];

// fp16 activation splits (GEMM A operands)
__device__ hlf g_xnh[BB*NN*DD],  g_xnl[BB*NN*DD];
__device__ hlf g_aoh[BB*NN*DD],  g_aol[BB*NN*DD];
__device__ hlf g_ffh[(size_t)BB*NN*FFI], g_ffl[(size_t)BB*NN*FFI];

// fp16 weights, transposed to [l][n][k] (GEMM B operands)
// qkv keeps hi+lo (3-pass: feeds softmax exp); others single fp16 (2-pass)
__device__ hlf g_wqkvh[LL*640*DD],  g_wqkvl[LL*640*DD];
__device__ hlf g_woh [LL*DD*DD];
__device__ hlf g_w1h [(size_t)LL*4096*DD];
__device__ hlf g_w2h [(size_t)LL*DD*FFI];
__device__ hlf g_wph [DD*DD];

__constant__ float c_invfreq[16] = {
    1.0f,           0.5623413252f,  0.3162277660f,  0.1778279410f,
    0.1f,           0.05623413252f, 0.03162277660f, 0.01778279410f,
    0.01f,          0.005623413252f,0.003162277660f,0.001778279410f,
    0.001f,         5.623413252e-4f,3.162277660e-4f,1.778279410e-4f};

// ---------------- helpers ----------------
__device__ __forceinline__ uint32_t smem_u32(const void* p) {
    uint32_t a;
    asm("{ .reg .u64 t; cvta.to.shared.u64 t, %1; cvt.u32.u64 %0, t; }" : "=r"(a) : "l"(p));
    return a;
}
__device__ __forceinline__ void cpa16(uint32_t s, const void* g) {
    asm volatile("cp.async.cg.shared.global [%0], [%1], 16;" :: "r"(s), "l"(g) : "memory");
}
__device__ __forceinline__ void ldsm4(uint32_t* r, uint32_t addr) {
    asm volatile("ldmatrix.sync.aligned.m8n8.x4.shared.b16 {%0,%1,%2,%3}, [%4];"
                 : "=r"(r[0]), "=r"(r[1]), "=r"(r[2]), "=r"(r[3]) : "r"(addr));
}
__device__ __forceinline__ void mma16816(float* d, const uint32_t* a, const uint32_t* b) {
    asm volatile(
        "mma.sync.aligned.m16n8k16.row.col.f32.f16.f16.f32 "
        "{%0,%1,%2,%3}, {%4,%5,%6,%7}, {%8,%9}, {%0,%1,%2,%3};"
        : "+f"(d[0]), "+f"(d[1]), "+f"(d[2]), "+f"(d[3])
        : "r"(a[0]), "r"(a[1]), "r"(a[2]), "r"(a[3]), "r"(b[0]), "r"(b[1]));
}
// split fp32 pair -> f16x2 (hi) + f16x2 (lo residual); low half = first element
__device__ __forceinline__ void split2(float a0, float a1, uint32_t &hp, uint32_t &lp) {
    asm("cvt.rn.f16x2.f32 %0, %1, %2;" : "=r"(hp) : "f"(a1), "f"(a0));
    float h0 = __half2float(__ushort_as_half((unsigned short)(hp & 0xffffu)));
    float h1 = __half2float(__ushort_as_half((unsigned short)(hp >> 16)));
    float l0 = a0 - h0, l1 = a1 - h1;
    asm("cvt.rn.f16x2.f32 %0, %1, %2;" : "=r"(lp) : "f"(l1), "f"(l0));
}

// ---------------- small kernels ----------------
__global__ void copy_kernel(const float* __restrict__ src, float* __restrict__ dst, int n) {
    int i = blockIdx.x * blockDim.x + threadIdx.x;
    if (i < n) dst[i] = src[i];
}

__global__ void bias_kernel(const float* __restrict__ emb, float* __restrict__ bias) {
    int d = blockIdx.x * blockDim.x + threadIdx.x;
    if (d >= NKEY) return;
    int bkt;
    if (d < 16) {
        bkt = d;
    } else {
        int v = 16 + (int)(logf((float)d * (1.0f/16.0f)) / logf(8.0f) * 16.0f);
        bkt = v < 31 ? v : 31;
    }
    #pragma unroll
    for (int h = 0; h < HH; h++) bias[h*NKEY + d] = emb[bkt*HH + h];
}

// weight transpose+split: W[z][K][Nc] fp32 -> fp16 at out_base + z*out_lstride,
// layout [n'][K]; lo written only if non-null. perm=1: a/gate interleave.
__global__ __launch_bounds__(256) void wsplit_kernel(
    const float* __restrict__ W, hlf* __restrict__ hi, hlf* __restrict__ lo,
    int K, int Nc, size_t out_lstride, size_t out_base, int perm)
{
    __shared__ float tile[32][33];
    const size_t lstr = (size_t)K * Nc;
    const float* Wl = W + lstr * blockIdx.z;
    const size_t ob = out_base + out_lstride * blockIdx.z;
    int n0 = blockIdx.x * 32, k0 = blockIdx.y * 32;
    #pragma unroll
    for (int r = threadIdx.y; r < 32; r += 8)
        tile[r][threadIdx.x] = Wl[(size_t)(k0 + r) * Nc + n0 + threadIdx.x];
    __syncthreads();
    #pragma unroll
    for (int r = threadIdx.y; r < 32; r += 8) {
        float w = tile[threadIdx.x][r];
        hlf h = __float2half_rn(w);
        int n = n0 + r;
        int np = perm ? ((n < 2048) ? (n << 1) : (((n - 2048) << 1) | 1)) : n;
        size_t o = ob + (size_t)np * K + k0 + threadIdx.x;
        hi[o] = h;
        if (lo) lo[o] = __float2half_rn(w - __half2float(h));
    }
}

// LayerNorm. If outf: out fp32 = base + LN(in)*g (residual). Else fp16 hi/lo split.
__global__ __launch_bounds__(128) void ln_kernel(
    const float* __restrict__ in, const float* __restrict__ g,
    const float* __restrict__ base, float* __restrict__ outf,
    hlf* __restrict__ outh, hlf* __restrict__ outl, int stable)
{
    int row  = blockIdx.x;
    int t    = threadIdx.x;
    int lane = t & 31, wid = t >> 5;
    const float* rp = in + (size_t)row * DD;
    float4 v = *(const float4*)(rp + t*4);
    __shared__ float red[8];

    if (stable) {
        float mx = fmaxf(fmaxf(v.x, v.y), fmaxf(v.z, v.w));
        #pragma unroll
        for (int o = 16; o; o >>= 1) mx = fmaxf(mx, __shfl_xor_sync(0xffffffffu, mx, o));
        if (lane == 0) red[wid] = mx;
        __syncthreads();
        mx = fmaxf(fmaxf(red[0], red[1]), fmaxf(red[2], red[3]));
        __syncthreads();
        v.x /= mx; v.y /= mx; v.z /= mx; v.w /= mx;
    }
    float s = v.x + v.y + v.z + v.w;
    float q = v.x*v.x + v.y*v.y + v.z*v.z + v.w*v.w;
    #pragma unroll
    for (int o = 16; o; o >>= 1) {
        s += __shfl_xor_sync(0xffffffffu, s, o);
        q += __shfl_xor_sync(0xffffffffu, q, o);
    }
    if (lane == 0) { red[wid] = s; red[4+wid] = q; }
    __syncthreads();
    float mean = (red[0]+red[1]+red[2]+red[3]) * (1.0f/(float)DD);
    float msq  = (red[4]+red[5]+red[6]+red[7]) * (1.0f/(float)DD);
    float rstd = rsqrtf(msq - mean*mean + 1e-5f);
    float4 gg = *(const float4*)(g + t*4);
    float4 o4;
    o4.x = (v.x - mean) * rstd * gg.x;
    o4.y = (v.y - mean) * rstd * gg.y;
    o4.z = (v.z - mean) * rstd * gg.z;
    o4.w = (v.w - mean) * rstd * gg.w;
    size_t off = (size_t)row*DD + t*4;
    if (outf) {
        float4 b4 = *(const float4*)(base + off);
        o4.x += b4.x; o4.y += b4.y; o4.z += b4.z; o4.w += b4.w;
        *(float4*)(outf + off) = o4;
    } else {
        uint32_t h0, l0, h1, l1;
        split2(o4.x, o4.y, h0, l0);
        split2(o4.z, o4.w, h1, l1);
        *(uint2*)(outh + off) = make_uint2(h0, h1);
        *(uint2*)(outl + off) = make_uint2(l0, l1);
    }
}

// Fused: xnew = xres + LN(in)*g1 -> xres;  LN(xnew)*g2 -> fp16 hi/lo split.
__global__ __launch_bounds__(128) void ln_add_ln_kernel(
    const float* __restrict__ in, const float* __restrict__ g1,
    const float* __restrict__ g2, float* __restrict__ xres,
    hlf* __restrict__ outh, hlf* __restrict__ outl)
{
    int row  = blockIdx.x;
    int t    = threadIdx.x;
    int lane = t & 31, wid = t >> 5;
    size_t off = (size_t)row*DD + t*4;
    float4 v = *(const float4*)(in + off);
    __shared__ float red[8];

    float s = v.x + v.y + v.z + v.w;
    float q = v.x*v.x + v.y*v.y + v.z*v.z + v.w*v.w;
    #pragma unroll
    for (int o = 16; o; o >>= 1) {
        s += __shfl_xor_sync(0xffffffffu, s, o);
        q += __shfl_xor_sync(0xffffffffu, q, o);
    }
    if (lane == 0) { red[wid] = s; red[4+wid] = q; }
    __syncthreads();
    float mean = (red[0]+red[1]+red[2]+red[3]) * (1.0f/(float)DD);
    float msq  = (red[4]+red[5]+red[6]+red[7]) * (1.0f/(float)DD);
    float rstd = rsqrtf(msq - mean*mean + 1e-5f);
    float4 gg = *(const float4*)(g1 + t*4);
    float4 b4 = *(const float4*)(xres + off);
    float4 x4;
    x4.x = b4.x + (v.x - mean) * rstd * gg.x;
    x4.y = b4.y + (v.y - mean) * rstd * gg.y;
    x4.z = b4.z + (v.z - mean) * rstd * gg.z;
    x4.w = b4.w + (v.w - mean) * rstd * gg.w;
    *(float4*)(xres + off) = x4;
    __syncthreads();              // red[] reuse

    float s2 = x4.x + x4.y + x4.z + x4.w;
    float q2 = x4.x*x4.x + x4.y*x4.y + x4.z*x4.z + x4.w*x4.w;
    #pragma unroll
    for (int o = 16; o; o >>= 1) {
        s2 += __shfl_xor_sync(0xffffffffu, s2, o);
        q2 += __shfl_xor_sync(0xffffffffu, q2, o);
    }
    if (lane == 0) { red[wid] = s2; red[4+wid] = q2; }
    __syncthreads();
    float mean2 = (red[0]+red[1]+red[2]+red[3]) * (1.0f/(float)DD);
    float msq2  = (red[4]+red[5]+red[6]+red[7]) * (1.0f/(float)DD);
    float rstd2 = rsqrtf(msq2 - mean2*mean2 + 1e-5f);
    float4 g2v = *(const float4*)(g2 + t*4);
    float4 o4;
    o4.x = (x4.x - mean2) * rstd2 * g2v.x;
    o4.y = (x4.y - mean2) * rstd2 * g2v.y;
    o4.z = (x4.z - mean2) * rstd2 * g2v.z;
    o4.w = (x4.w - mean2) * rstd2 * g2v.w;
    uint32_t h0, l0, h1, l1;
    split2(o4.x, o4.y, h0, l0);
    split2(o4.z, o4.w, h1, l1);
    *(uint2*)(outh + off) = make_uint2(h0, h1);
    *(uint2*)(outl + off) = make_uint2(l0, l1);
}

// ---------------- tensor-core GEMM (fp16 split, NP passes) --------------------
#define TCG_SMEM (131072 + 1024)

extern __shared__ char dsm[];

template<int NP>
__global__ __launch_bounds__(256)
void tc_gemm_t(const hlf* __restrict__ Ahi, const hlf* __restrict__ Alo,
               const hlf* __restrict__ Bhi, const hlf* __restrict__ Blo,
               float* __restrict__ C, const float* __restrict__ addsrc,
               hlf* __restrict__ Oh, hlf* __restrict__ Ol,
               int K, int Nc, int glu)
{
    const int tid  = threadIdx.x;
    const int wid  = tid >> 5;
    const int lane = tid & 31;
    const int m0 = blockIdx.y * 128, n0 = blockIdx.x * 128;

    uint32_t sbase = smem_u32(dsm);
    uint32_t bufu  = (sbase + 1023) & ~1023u;

    const int wm = wid & 1;
    const int wn = wid >> 1;
    const int lr = lane & 15;
    const int lk = (lane >> 4) << 4;
    const uint32_t xorv = (uint32_t)(lr & 7) << 4;

    float acc[4][4][4];
    #pragma unroll
    for (int i = 0; i < 4; i++)
        #pragma unroll
        for (int j = 0; j < 4; j++)
            #pragma unroll
            for (int r = 0; r < 4; r++) acc[i][j][r] = 0.f;

    const int nch = K >> 6;
    const int lrow = tid >> 3;
    const int lkk  = (tid & 7) << 3;
    uint32_t loff[4];
    #pragma unroll
    for (int it = 0; it < 4; it++) {
        uint32_t off = (uint32_t)(((lrow + it*32) << 7) + (lkk << 1));
        loff[it] = off ^ ((off >> 3) & 0x70u);
    }

    auto LOAD = [&](int c, int st) {
        const int k0 = c << 6;
        const uint32_t bs = bufu + st*65536;
        #pragma unroll
        for (int it = 0; it < 4; it++) {
            int row = lrow + it*32;
            size_t ga = (size_t)(m0 + row) * K + k0 + lkk;
            size_t gb = (size_t)(n0 + row) * K + k0 + lkk;
            cpa16(bs + loff[it],          Ahi + ga);
            cpa16(bs + 16384 + loff[it],  Alo + ga);
            cpa16(bs + 32768 + loff[it],  Bhi + gb);
            if (NP == 3)
                cpa16(bs + 49152 + loff[it], Blo + gb);
        }
        asm volatile("cp.async.commit_group;" ::: "memory");
    };

    LOAD(0, 0);

    for (int c = 0; c < nch; c++) {
        const int p = c & 1;
        if (c + 1 < nch) {
            LOAD(c + 1, 1 - p);
            asm volatile("cp.async.wait_group 1;" ::: "memory");
        } else {
            asm volatile("cp.async.wait_group 0;" ::: "memory");
        }
        __syncthreads();

        const uint32_t bA = bufu + p*65536;
        const uint32_t bB = bA + 32768;
        #pragma unroll
        for (int ks = 0; ks < 4; ks++) {
            const uint32_t koff = ((uint32_t)(ks*32 + lk)) ^ xorv;
            uint32_t bh[4][2], bl[4][2];
            #pragma unroll
            for (int bt = 0; bt < 2; bt++) {
                uint32_t r4[4];
                uint32_t baddr = bB + (uint32_t)((wn*32 + bt*16 + lr) << 7) + koff;
                ldsm4(r4, baddr);
                bh[bt*2][0]=r4[0]; bh[bt*2+1][0]=r4[1]; bh[bt*2][1]=r4[2]; bh[bt*2+1][1]=r4[3];
                if (NP == 3) {
                    ldsm4(r4, baddr + 16384);
                    bl[bt*2][0]=r4[0]; bl[bt*2+1][0]=r4[1]; bl[bt*2][1]=r4[2]; bl[bt*2+1][1]=r4[3];
                }
            }
            #pragma unroll
            for (int mt = 0; mt < 4; mt++) {
                uint32_t ah[4], al[4];
                uint32_t aaddr = bA + (uint32_t)((wm*64 + mt*16 + lr) << 7) + koff;
                ldsm4(ah, aaddr);
                ldsm4(al, aaddr + 16384);
                #pragma unroll
                for (int nt = 0; nt < 4; nt++) {
                    mma16816(acc[mt][nt], ah, bh[nt]);
                    if (NP == 3) mma16816(acc[mt][nt], ah, bl[nt]);
                    mma16816(acc[mt][nt], al, bh[nt]);
                }
            }
        }
        __syncthreads();
    }

    const int crow = lane >> 2;
    const int ccol = (lane & 3) << 1;
    if (glu) {
        const int half = Nc >> 1;
        #pragma unroll
        for (int mt = 0; mt < 4; mt++) {
            #pragma unroll
            for (int nt = 0; nt < 4; nt++) {
                int m  = m0 + wm*64 + mt*16 + crow;
                int n  = n0 + wn*32 + nt*8  + ccol;
                int oc = n >> 1;
                float a0 = acc[mt][nt][0], gt0 = acc[mt][nt][1];
                float a1 = acc[mt][nt][2], gt1 = acc[mt][nt][3];
                float r0 = a0 * gt0 / (1.0f + __expf(-gt0));
                float r1 = a1 * gt1 / (1.0f + __expf(-gt1));
                hlf h0 = __float2half_rn(r0);
                hlf h1 = __float2half_rn(r1);
                size_t o0 = (size_t)m*half + oc;
                size_t o1 = o0 + (size_t)8*half;
                Oh[o0] = h0; Ol[o0] = __float2half_rn(r0 - __half2float(h0));
                Oh[o1] = h1; Ol[o1] = __float2half_rn(r1 - __half2float(h1));
            }
        }
        return;
    }
    #pragma unroll
    for (int mt = 0; mt < 4; mt++) {
        #pragma unroll
        for (int nt = 0; nt < 4; nt++) {
            int m = m0 + wm*64 + mt*16 + crow;
            int n = n0 + wn*32 + nt*8  + ccol;
            size_t o0 = (size_t)m*Nc + n;
            size_t o1 = o0 + (size_t)8*Nc;
            float2 v0 = make_float2(acc[mt][nt][0], acc[mt][nt][1]);
            float2 v1 = make_float2(acc[mt][nt][2], acc[mt][nt][3]);
            if (addsrc) {
                float2 s0 = *(const float2*)(addsrc + o0);
                float2 s1 = *(const float2*)(addsrc + o1);
                v0.x += s0.x; v0.y += s0.y; v1.x += s1.x; v1.y += s1.y;
            }
            *(float2*)(C + o0) = v0;
            *(float2*)(C + o1) = v1;
        }
    }
}

// ---------------- merged q/k/v prep (fp32 outputs; q and kv paths concurrent) --
#define QWARPS (BB*NN*HH)              // 32768
#define KVWARPS (BB*NKEY)              // 4100
__global__ __launch_bounds__(256) void prep_qkv_kernel(
    const float* __restrict__ qkv, const float* __restrict__ nullkv_l,
    float* __restrict__ q, float* __restrict__ kb, float* __restrict__ vb)
{
    int w = (blockIdx.x * blockDim.x + threadIdx.x) >> 5;
    int t = threadIdx.x & 31;
    if (w < QWARPS) {
        int h  = w & 7;
        int bi = w >> 3;
        int i  = bi & (NN - 1);
        const float* src = qkv + (size_t)bi*640 + h*DHH;
        float e0 = src[t], e1 = src[32+t];
        float ang = (float)i * c_invfreq[t >> 1];
        float c, sn;
        sincosf(ang, &sn, &c);
        float partner = __shfl_xor_sync(0xffffffffu, e0, 1);
        e0 = (t & 1) ? (e0*c + partner*sn) : (e0*c - partner*sn);
        float ss = e0*e0 + e1*e1;
        #pragma unroll
        for (int o = 16; o; o >>= 1) ss += __shfl_xor_sync(0xffffffffu, ss, o);
        float scale = 4.0f / fmaxf(sqrtf(ss), 1e-12f);
        float* dst = q + (size_t)bi*DD + h*DHH;
        dst[t]    = e0 * scale;
        dst[32+t] = e1 * scale;
    } else if (w < QWARPS + KVWARPS) {
        int w2 = w - QWARPS;
        int b = w2 / NKEY;
        int i = w2 - b*NKEY;
        float k0, k1, v0, v1;
        if (i == 0) {
            k0 = nullkv_l[t];    k1 = nullkv_l[32+t];
            v0 = nullkv_l[64+t]; v1 = nullkv_l[96+t];
        } else {
            const float* rp = qkv + ((size_t)b*NN + (i-1))*640 + 512;
            k0 = rp[t]; k1 = rp[32+t]; v0 = rp[64+t]; v1 = rp[96+t];
            float ang = (float)(i-1) * c_invfreq[t >> 1];
            float c, sn;
            sincosf(ang, &sn, &c);
            float partner = __shfl_xor_sync(0xffffffffu, k0, 1);
            k0 = (t & 1) ? (k0*c + partner*sn) : (k0*c - partner*sn);
        }
        float ss = k0*k0 + k1*k1;
        #pragma unroll
        for (int o = 16; o; o >>= 1) ss += __shfl_xor_sync(0xffffffffu, ss, o);
        float scale = 4.0f / fmaxf(sqrtf(ss), 1e-12f);
        size_t off = ((size_t)b*NKEY + i)*DHH;
        kb[off+t]    = k0 * scale;
        kb[off+32+t] = k1 * scale;
        vb[off+t]    = v0;
        vb[off+32+t] = v1;
    }
}

// ---------------- attention (R13 algorithm, 16-query strips) -------------------
// Block = (b, 16-query strip), 8 warps = 8 heads. K/V tiles in smem shared
// across heads; 16 queries amortize each tile load. Reversed block order puts
// the longest causal blocks first. smem (floats):
//   qsT[h][d][qi16] 8192 | kT[d][j65] 4160 | vs[j][d] 4096 | psT[h][qi16][j64] 8192
#define QS 16
#define ATT_SMEM ((8192 + 64*65 + 4096 + 8192) * 4)

__global__ __launch_bounds__(256) void attn_kernel(
    const float* __restrict__ qn, const float* __restrict__ kb,
    const float* __restrict__ vb, const float* __restrict__ bias,
    hlf* __restrict__ oh, hlf* __restrict__ ol)
{
    float* qsT = (float*)dsm;            // 8192
    float* kT  = qsT + 8192;             // 64*65
    float* vs  = kT + 64*65;             // 4096
    float* psT = vs + 4096;              // 8192

    const int b   = blockIdx.y;
    const int i0  = (gridDim.x - 1 - blockIdx.x) * QS;   // longest blocks first
    const int tid = threadIdx.x;
    const int h   = tid >> 5;
    const int t   = tid & 31;

    // stage q strip: qsT[h][d][qi]
    for (int idx = tid; idx < 8192; idx += 256) {
        int qi = idx & 15, d = (idx >> 4) & 63, hh = idx >> 10;
        qsT[hh*1024 + d*16 + qi] = qn[((size_t)b*NN + i0 + qi)*DD + hh*64 + d];
    }

    float lsum[QS], acc0[QS], acc1[QS];
    #pragma unroll
    for (int qi = 0; qi < QS; qi++) { lsum[qi] = 0.f; acc0[qi] = 0.f; acc1[qi] = 0.f; }

    const float* qrow = qsT + h*1024;
    float*       pw   = psT + h*1024;    // [qi][64]
    const float* brow = bias + h*NKEY;

    int nkeys  = i0 + QS + 2; if (nkeys > NKEY) nkeys = NKEY;   // j in [0, i0+QS]
    int ntiles = (nkeys + 63) >> 6;

    __syncthreads();   // qsT ready

    for (int jt = 0; jt < ntiles; jt++) {
        const int jbase = jt << 6;
        // load K (transposed) + V tile
        for (int idx = tid; idx < 4096; idx += 256) {
            int r = idx >> 6, c = idx & 63;
            int j = jbase + r;
            float kk = 0.f, vv = 0.f;
            if (j < NKEY) {
                size_t so = ((size_t)b*NKEY + j)*DHH + c;
                kk = kb[so]; vv = vb[so];
            }
            kT[c*65 + r] = kk;
            vs[r*64 + c] = vv;
        }
        __syncthreads();

        // ---- QK: lane owns keys j1=jbase+t, j2=jbase+32+t ----
        float s1[QS], s2[QS];
        #pragma unroll
        for (int qi = 0; qi < QS; qi++) { s1[qi] = 0.f; s2[qi] = 0.f; }
        #pragma unroll 2
        for (int d = 0; d < 64; d++) {
            float ka = kT[d*65 + t];
            float kc = kT[d*65 + 32 + t];
            const float* qp = qrow + d*16;
            #pragma unroll
            for (int qq = 0; qq < 4; qq++) {
                float4 qv = *(const float4*)(qp + qq*4);
                s1[qq*4+0] = fmaf(qv.x, ka, s1[qq*4+0]); s2[qq*4+0] = fmaf(qv.x, kc, s2[qq*4+0]);
                s1[qq*4+1] = fmaf(qv.y, ka, s1[qq*4+1]); s2[qq*4+1] = fmaf(qv.y, kc, s2[qq*4+1]);
                s1[qq*4+2] = fmaf(qv.z, ka, s1[qq*4+2]); s2[qq*4+2] = fmaf(qv.z, kc, s2[qq*4+2]);
                s1[qq*4+3] = fmaf(qv.w, ka, s1[qq*4+3]); s2[qq*4+3] = fmaf(qv.w, kc, s2[qq*4+3]);
            }
        }

        // ---- softmax numerators (fixed max 16.5; logits bounded ~16.1) ----
        const int j1 = jbase + t, j2 = jbase + 32 + t;
        #pragma unroll
        for (int qi = 0; qi < QS; qi++) {
            int i = i0 + qi;
            float e1 = 0.f, e2 = 0.f;
            if (j1 <= i + 1 && j1 < NKEY) {
                int d = i - j1; d = d < 0 ? 0 : d;
                e1 = __expf(s1[qi] + __ldg(brow + d) - 16.5f);
            }
            if (j2 <= i + 1 && j2 < NKEY) {
                int d = i - j2; d = d < 0 ? 0 : d;
                e2 = __expf(s2[qi] + __ldg(brow + d) - 16.5f);
            }
            lsum[qi] += e1 + e2;
            pw[qi*64 + t]      = e1;
            pw[qi*64 + 32 + t] = e2;
        }
        __syncwarp();

        // ---- PV: lane owns dims t, 32+t ----
        int jmax = nkeys - jbase; if (jmax > 64) jmax = 64;
        for (int j = 0; j < jmax; j++) {
            float v0 = vs[j*64 + t];
            float v1 = vs[j*64 + 32 + t];
            #pragma unroll
            for (int qi = 0; qi < QS; qi++) {
                float pj = pw[qi*64 + j];
                acc0[qi] = fmaf(pj, v0, acc0[qi]);
                acc1[qi] = fmaf(pj, v1, acc1[qi]);
            }
        }
        __syncthreads();   // before next tile overwrites kT/vs
    }

    // reduce lane-partial lsum across warp, write fp16 hi/lo out
    #pragma unroll
    for (int qi = 0; qi < QS; qi++) {
        float s = lsum[qi];
        #pragma unroll
        for (int off = 16; off; off >>= 1) s += __shfl_xor_sync(0xffffffffu, s, off);
        float inv = 1.0f / s;
        float v0 = acc0[qi] * inv;
        float v1 = acc1[qi] * inv;
        size_t off2 = ((size_t)b*NN + i0 + qi)*DD + h*DHH;
        hlf h0 = __float2half_rn(v0);
        hlf h1 = __float2half_rn(v1);
        oh[off2 + t]      = h0;
        oh[off2 + 32 + t] = h1;
        ol[off2 + t]      = __float2half_rn(v0 - __half2float(h0));
        ol[off2 + 32 + t] = __float2half_rn(v1 - __half2float(h1));
    }
}

// ---------------- host ----------------
extern "C" void kernel_launch(void* const* d_in, const int* in_sizes, int n_in,
                              void* d_out, int out_size)
{
    const float* x         = (const float*)d_in[0];
    const float* emb       = (const float*)d_in[1];
    const float* g_attn    = (const float*)d_in[2];
    const float* null_kv   = (const float*)d_in[3];
    const float* Wq        = (const float*)d_in[4];
    const float* Wkv       = (const float*)d_in[5];
    const float* Wo        = (const float*)d_in[6];
    const float* g_attn_o  = (const float*)d_in[7];
    const float* g_ff_     = (const float*)d_in[8];
    const float* W1        = (const float*)d_in[9];
    const float* W2        = (const float*)d_in[10];
    const float* g_final   = (const float*)d_in[11];
    const float* Wproj     = (const float*)d_in[12];
    float* out = (float*)d_out;

    void *p;
    cudaGetSymbolAddress(&p, g_x);    float* xb  = (float*)p;
    cudaGetSymbolAddress(&p, g_qkv);  float* qkvb= (float*)p;
    cudaGetSymbolAddress(&p, g_q);    float* qb  = (float*)p;
    cudaGetSymbolAddress(&p, g_k);    float* kbb = (float*)p;
    cudaGetSymbolAddress(&p, g_v);    float* vbb = (float*)p;
    cudaGetSymbolAddress(&p, g_pr);   float* prb = (float*)p;
    cudaGetSymbolAddress(&p, g_bias); float* bib = (float*)p;
    cudaGetSymbolAddress(&p, g_xnh);  hlf* xnh = (hlf*)p;
    cudaGetSymbolAddress(&p, g_xnl);  hlf* xnl = (hlf*)p;
    cudaGetSymbolAddress(&p, g_aoh);  hlf* aoh = (hlf*)p;
    cudaGetSymbolAddress(&p, g_aol);  hlf* aol = (hlf*)p;
    cudaGetSymbolAddress(&p, g_ffh);  hlf* ffh = (hlf*)p;
    cudaGetSymbolAddress(&p, g_ffl);  hlf* ffl = (hlf*)p;
    cudaGetSymbolAddress(&p, g_wqkvh);hlf* wqkvh=(hlf*)p;
    cudaGetSymbolAddress(&p, g_wqkvl);hlf* wqkvl=(hlf*)p;
    cudaGetSymbolAddress(&p, g_woh);  hlf* woh = (hlf*)p;
    cudaGetSymbolAddress(&p, g_w1h);  hlf* w1h = (hlf*)p;
    cudaGetSymbolAddress(&p, g_w2h);  hlf* w2h = (hlf*)p;
    cudaGetSymbolAddress(&p, g_wph);  hlf* wph = (hlf*)p;

    cudaFuncSetAttribute(tc_gemm_t<2>, cudaFuncAttributeMaxDynamicSharedMemorySize, TCG_SMEM);
    cudaFuncSetAttribute(tc_gemm_t<3>, cudaFuncAttributeMaxDynamicSharedMemorySize, TCG_SMEM);
    cudaFuncSetAttribute(attn_kernel, cudaFuncAttributeMaxDynamicSharedMemorySize, ATT_SMEM);

    const int M = BB * NN;           // 4096
    dim3 wb(32, 8);

    copy_kernel<<<(M*DD + 255)/256, 256>>>(x, xb, M*DD);
    bias_kernel<<<(NKEY + 255)/256, 256>>>(emb, bib);

    // weight transforms (fp32 [K][Nc] -> fp16 [n'][K]; qkv also lo)
    wsplit_kernel<<<dim3(16, 16, LL), wb>>>(Wq,   wqkvh, wqkvl, DD, DD,  (size_t)640*DD, 0,              0);
    wsplit_kernel<<<dim3(4,  16, LL), wb>>>(Wkv,  wqkvh, wqkvl, DD, 128, (size_t)640*DD, (size_t)512*DD, 0);
    wsplit_kernel<<<dim3(16, 16, LL), wb>>>(Wo,   woh,  nullptr, DD, DD,   (size_t)DD*DD, 0, 0);
    wsplit_kernel<<<dim3(128,16, LL), wb>>>(W1,   w1h,  nullptr, DD, 4096, (size_t)4096*DD, 0, 1);  // a/gate interleave
    wsplit_kernel<<<dim3(16, 64, LL), wb>>>(W2,   w2h,  nullptr, FFI, DD,  (size_t)DD*FFI, 0, 0);
    wsplit_kernel<<<dim3(16, 16, 1),  wb>>>(Wproj,wph,  nullptr, DD, DD,   0, 0, 0);

    const int prep_blocks = (QWARPS + KVWARPS + 7) / 8;

    for (int l = 0; l < LL; l++) {
        // attention block
        ln_kernel<<<M, 128>>>(xb, g_attn + l*DD, nullptr, nullptr, xnh, xnl, 0);
        tc_gemm_t<3><<<dim3(5, 32), 256, TCG_SMEM>>>(xnh, xnl,
            wqkvh + (size_t)l*640*DD, wqkvl + (size_t)l*640*DD,
            qkvb, nullptr, nullptr, nullptr, DD, 640, 0);
        prep_qkv_kernel<<<prep_blocks, 256>>>(qkvb, null_kv + l*2*DHH, qb, kbb, vbb);
        attn_kernel<<<dim3(NN/QS, BB), 256, ATT_SMEM>>>(qb, kbb, vbb, bib, aoh, aol);
        tc_gemm_t<2><<<dim3(4, 32), 256, TCG_SMEM>>>(aoh, aol,
            woh + (size_t)l*DD*DD, nullptr,
            prb, nullptr, nullptr, nullptr, DD, DD, 0);
        // x += LN(o@Wo); xn = LN(x) for FF  (fused)
        ln_add_ln_kernel<<<M, 128>>>(prb, g_attn_o + l*DD, g_ff_ + l*DD, xb, xnh, xnl);
        // feed-forward block: W1 with fused GLU epilogue -> ffh/ffl
        tc_gemm_t<2><<<dim3(32, 32), 256, TCG_SMEM>>>(xnh, xnl,
            w1h + (size_t)l*4096*DD, nullptr,
            nullptr, nullptr, ffh, ffl, DD, 4096, 1);
        tc_gemm_t<2><<<dim3(4, 32), 256, TCG_SMEM>>>(ffh, ffl,
            w2h + (size_t)l*DD*FFI, nullptr,
            xb, xb, nullptr, nullptr, FFI, DD, 0);
    }
    ln_kernel<<<M, 128>>>(xb, g_final, nullptr, nullptr, xnh, xnl, 1);   // stable LN
    tc_gemm_t<2><<<dim3(4, 32), 256, TCG_SMEM>>>(xnh, xnl, wph, nullptr, out, nullptr,
                                                 nullptr, nullptr, DD, DD, 0);
}

// round 17
// speedup vs baseline: 1.1393x; 1.1393x over previous
#include <cuda_runtime.h>
#include <cuda_fp16.h>
#include <math.h>
#include <stdint.h>

// Problem constants
#define BB 4
#define NN 1024
#define DD 512
#define LL 6
#define HH 8
#define DHH 64
#define FFI 2048          // FF_INNER
#define NKEY 1025         // N + 1 (null key prepended)

typedef __half hlf;

// ---------------- static device scratch ----------------
__device__ float g_x  [BB*NN*DD];       // residual stream
__device__ float g_qkv[BB*NN*640];      // fused q|k|v GEMM output
__device__ float g_q  [BB*NN*DD];       // rotated+normalized q
__device__ float g_k  [BB*NKEY*DHH];
__device__ float g_v  [BB*NKEY*DHH];
__device__ float g_pr [BB*NN*DD];
__device__ float g_bias[HH*NKEY];

// fp16 activation splits (GEMM A operands)
__device__ hlf g_xnh[BB*NN*DD],  g_xnl[BB*NN*DD];
__device__ hlf g_aoh[BB*NN*DD],  g_aol[BB*NN*DD];
__device__ hlf g_ffh[(size_t)BB*NN*FFI], g_ffl[(size_t)BB*NN*FFI];

// fp16 weights, transposed to [l][n][k] (GEMM B operands)
// qkv keeps hi+lo (3-pass: feeds softmax exp); others single fp16 (2-pass)
__device__ hlf g_wqkvh[LL*640*DD],  g_wqkvl[LL*640*DD];
__device__ hlf g_woh [LL*DD*DD];
__device__ hlf g_w1h [(size_t)LL*4096*DD];
__device__ hlf g_w2h [(size_t)LL*DD*FFI];
__device__ hlf g_wph [DD*DD];

__constant__ float c_invfreq[16] = {
    1.0f,           0.5623413252f,  0.3162277660f,  0.1778279410f,
    0.1f,           0.05623413252f, 0.03162277660f, 0.01778279410f,
    0.01f,          0.005623413252f,0.003162277660f,0.001778279410f,
    0.001f,         5.623413252e-4f,3.162277660e-4f,1.778279410e-4f};

// ---------------- helpers ----------------
__device__ __forceinline__ uint32_t smem_u32(const void* p) {
    uint32_t a;
    asm("{ .reg .u64 t; cvta.to.shared.u64 t, %1; cvt.u32.u64 %0, t; }" : "=r"(a) : "l"(p));
    return a;
}
__device__ __forceinline__ void cpa16(uint32_t s, const void* g) {
    asm volatile("cp.async.cg.shared.global [%0], [%1], 16;" :: "r"(s), "l"(g) : "memory");
}
__device__ __forceinline__ void ldsm4(uint32_t* r, uint32_t addr) {
    asm volatile("ldmatrix.sync.aligned.m8n8.x4.shared.b16 {%0,%1,%2,%3}, [%4];"
                 : "=r"(r[0]), "=r"(r[1]), "=r"(r[2]), "=r"(r[3]) : "r"(addr));
}
__device__ __forceinline__ void mma16816(float* d, const uint32_t* a, const uint32_t* b) {
    asm volatile(
        "mma.sync.aligned.m16n8k16.row.col.f32.f16.f16.f32 "
        "{%0,%1,%2,%3}, {%4,%5,%6,%7}, {%8,%9}, {%0,%1,%2,%3};"
        : "+f"(d[0]), "+f"(d[1]), "+f"(d[2]), "+f"(d[3])
        : "r"(a[0]), "r"(a[1]), "r"(a[2]), "r"(a[3]), "r"(b[0]), "r"(b[1]));
}
// split fp32 pair -> f16x2 (hi) + f16x2 (lo residual); low half = first element
__device__ __forceinline__ void split2(float a0, float a1, uint32_t &hp, uint32_t &lp) {
    asm("cvt.rn.f16x2.f32 %0, %1, %2;" : "=r"(hp) : "f"(a1), "f"(a0));
    float h0 = __half2float(__ushort_as_half((unsigned short)(hp & 0xffffu)));
    float h1 = __half2float(__ushort_as_half((unsigned short)(hp >> 16)));
    float l0 = a0 - h0, l1 = a1 - h1;
    asm("cvt.rn.f16x2.f32 %0, %1, %2;" : "=r"(lp) : "f"(l1), "f"(l0));
}

// ---------------- small kernels ----------------
__global__ void copy_kernel(const float* __restrict__ src, float* __restrict__ dst, int n) {
    int i = blockIdx.x * blockDim.x + threadIdx.x;
    if (i < n) dst[i] = src[i];
}

__global__ void bias_kernel(const float* __restrict__ emb, float* __restrict__ bias) {
    int d = blockIdx.x * blockDim.x + threadIdx.x;
    if (d >= NKEY) return;
    int bkt;
    if (d < 16) {
        bkt = d;
    } else {
        int v = 16 + (int)(logf((float)d * (1.0f/16.0f)) / logf(8.0f) * 16.0f);
        bkt = v < 31 ? v : 31;
    }
    #pragma unroll
    for (int h = 0; h < HH; h++) bias[h*NKEY + d] = emb[bkt*HH + h];
}

// weight transpose+split: W[z][K][Nc] fp32 -> fp16 at out_base + z*out_lstride,
// layout [n'][K]; lo written only if non-null. perm=1: a/gate interleave.
__global__ __launch_bounds__(256) void wsplit_kernel(
    const float* __restrict__ W, hlf* __restrict__ hi, hlf* __restrict__ lo,
    int K, int Nc, size_t out_lstride, size_t out_base, int perm)
{
    __shared__ float tile[32][33];
    const size_t lstr = (size_t)K * Nc;
    const float* Wl = W + lstr * blockIdx.z;
    const size_t ob = out_base + out_lstride * blockIdx.z;
    int n0 = blockIdx.x * 32, k0 = blockIdx.y * 32;
    #pragma unroll
    for (int r = threadIdx.y; r < 32; r += 8)
        tile[r][threadIdx.x] = Wl[(size_t)(k0 + r) * Nc + n0 + threadIdx.x];
    __syncthreads();
    #pragma unroll
    for (int r = threadIdx.y; r < 32; r += 8) {
        float w = tile[threadIdx.x][r];
        hlf h = __float2half_rn(w);
        int n = n0 + r;
        int np = perm ? ((n < 2048) ? (n << 1) : (((n - 2048) << 1) | 1)) : n;
        size_t o = ob + (size_t)np * K + k0 + threadIdx.x;
        hi[o] = h;
        if (lo) lo[o] = __float2half_rn(w - __half2float(h));
    }
}

// LayerNorm. If outf: out fp32 = base + LN(in)*g (residual). Else fp16 hi/lo split.
__global__ __launch_bounds__(128) void ln_kernel(
    const float* __restrict__ in, const float* __restrict__ g,
    const float* __restrict__ base, float* __restrict__ outf,
    hlf* __restrict__ outh, hlf* __restrict__ outl, int stable)
{
    int row  = blockIdx.x;
    int t    = threadIdx.x;
    int lane = t & 31, wid = t >> 5;
    const float* rp = in + (size_t)row * DD;
    float4 v = *(const float4*)(rp + t*4);
    __shared__ float red[8];

    if (stable) {
        float mx = fmaxf(fmaxf(v.x, v.y), fmaxf(v.z, v.w));
        #pragma unroll
        for (int o = 16; o; o >>= 1) mx = fmaxf(mx, __shfl_xor_sync(0xffffffffu, mx, o));
        if (lane == 0) red[wid] = mx;
        __syncthreads();
        mx = fmaxf(fmaxf(red[0], red[1]), fmaxf(red[2], red[3]));
        __syncthreads();
        v.x /= mx; v.y /= mx; v.z /= mx; v.w /= mx;
    }
    float s = v.x + v.y + v.z + v.w;
    float q = v.x*v.x + v.y*v.y + v.z*v.z + v.w*v.w;
    #pragma unroll
    for (int o = 16; o; o >>= 1) {
        s += __shfl_xor_sync(0xffffffffu, s, o);
        q += __shfl_xor_sync(0xffffffffu, q, o);
    }
    if (lane == 0) { red[wid] = s; red[4+wid] = q; }
    __syncthreads();
    float mean = (red[0]+red[1]+red[2]+red[3]) * (1.0f/(float)DD);
    float msq  = (red[4]+red[5]+red[6]+red[7]) * (1.0f/(float)DD);
    float rstd = rsqrtf(msq - mean*mean + 1e-5f);
    float4 gg = *(const float4*)(g + t*4);
    float4 o4;
    o4.x = (v.x - mean) * rstd * gg.x;
    o4.y = (v.y - mean) * rstd * gg.y;
    o4.z = (v.z - mean) * rstd * gg.z;
    o4.w = (v.w - mean) * rstd * gg.w;
    size_t off = (size_t)row*DD + t*4;
    if (outf) {
        float4 b4 = *(const float4*)(base + off);
        o4.x += b4.x; o4.y += b4.y; o4.z += b4.z; o4.w += b4.w;
        *(float4*)(outf + off) = o4;
    } else {
        uint32_t h0, l0, h1, l1;
        split2(o4.x, o4.y, h0, l0);
        split2(o4.z, o4.w, h1, l1);
        *(uint2*)(outh + off) = make_uint2(h0, h1);
        *(uint2*)(outl + off) = make_uint2(l0, l1);
    }
}

// Fused: xnew = xres + LN(in)*g1 -> xres;  LN(xnew)*g2 -> fp16 hi/lo split.
__global__ __launch_bounds__(128) void ln_add_ln_kernel(
    const float* __restrict__ in, const float* __restrict__ g1,
    const float* __restrict__ g2, float* __restrict__ xres,
    hlf* __restrict__ outh, hlf* __restrict__ outl)
{
    int row  = blockIdx.x;
    int t    = threadIdx.x;
    int lane = t & 31, wid = t >> 5;
    size_t off = (size_t)row*DD + t*4;
    float4 v = *(const float4*)(in + off);
    __shared__ float red[8];

    float s = v.x + v.y + v.z + v.w;
    float q = v.x*v.x + v.y*v.y + v.z*v.z + v.w*v.w;
    #pragma unroll
    for (int o = 16; o; o >>= 1) {
        s += __shfl_xor_sync(0xffffffffu, s, o);
        q += __shfl_xor_sync(0xffffffffu, q, o);
    }
    if (lane == 0) { red[wid] = s; red[4+wid] = q; }
    __syncthreads();
    float mean = (red[0]+red[1]+red[2]+red[3]) * (1.0f/(float)DD);
    float msq  = (red[4]+red[5]+red[6]+red[7]) * (1.0f/(float)DD);
    float rstd = rsqrtf(msq - mean*mean + 1e-5f);
    float4 gg = *(const float4*)(g1 + t*4);
    float4 b4 = *(const float4*)(xres + off);
    float4 x4;
    x4.x = b4.x + (v.x - mean) * rstd * gg.x;
    x4.y = b4.y + (v.y - mean) * rstd * gg.y;
    x4.z = b4.z + (v.z - mean) * rstd * gg.z;
    x4.w = b4.w + (v.w - mean) * rstd * gg.w;
    *(float4*)(xres + off) = x4;
    __syncthreads();              // red[] reuse

    float s2 = x4.x + x4.y + x4.z + x4.w;
    float q2 = x4.x*x4.x + x4.y*x4.y + x4.z*x4.z + x4.w*x4.w;
    #pragma unroll
    for (int o = 16; o; o >>= 1) {
        s2 += __shfl_xor_sync(0xffffffffu, s2, o);
        q2 += __shfl_xor_sync(0xffffffffu, q2, o);
    }
    if (lane == 0) { red[wid] = s2; red[4+wid] = q2; }
    __syncthreads();
    float mean2 = (red[0]+red[1]+red[2]+red[3]) * (1.0f/(float)DD);
    float msq2  = (red[4]+red[5]+red[6]+red[7]) * (1.0f/(float)DD);
    float rstd2 = rsqrtf(msq2 - mean2*mean2 + 1e-5f);
    float4 g2v = *(const float4*)(g2 + t*4);
    float4 o4;
    o4.x = (x4.x - mean2) * rstd2 * g2v.x;
    o4.y = (x4.y - mean2) * rstd2 * g2v.y;
    o4.z = (x4.z - mean2) * rstd2 * g2v.z;
    o4.w = (x4.w - mean2) * rstd2 * g2v.w;
    uint32_t h0, l0, h1, l1;
    split2(o4.x, o4.y, h0, l0);
    split2(o4.z, o4.w, h1, l1);
    *(uint2*)(outh + off) = make_uint2(h0, h1);
    *(uint2*)(outl + off) = make_uint2(l0, l1);
}

// ---------------- tensor-core GEMM (fp16 split, NP passes) --------------------
#define TCG_SMEM (131072 + 1024)

extern __shared__ char dsm[];

template<int NP>
__global__ __launch_bounds__(256)
void tc_gemm_t(const hlf* __restrict__ Ahi, const hlf* __restrict__ Alo,
               const hlf* __restrict__ Bhi, const hlf* __restrict__ Blo,
               float* __restrict__ C, const float* __restrict__ addsrc,
               hlf* __restrict__ Oh, hlf* __restrict__ Ol,
               int K, int Nc, int glu)
{
    const int tid  = threadIdx.x;
    const int wid  = tid >> 5;
    const int lane = tid & 31;
    const int m0 = blockIdx.y * 128, n0 = blockIdx.x * 128;

    uint32_t sbase = smem_u32(dsm);
    uint32_t bufu  = (sbase + 1023) & ~1023u;

    const int wm = wid & 1;
    const int wn = wid >> 1;
    const int lr = lane & 15;
    const int lk = (lane >> 4) << 4;
    const uint32_t xorv = (uint32_t)(lr & 7) << 4;

    float acc[4][4][4];
    #pragma unroll
    for (int i = 0; i < 4; i++)
        #pragma unroll
        for (int j = 0; j < 4; j++)
            #pragma unroll
            for (int r = 0; r < 4; r++) acc[i][j][r] = 0.f;

    const int nch = K >> 6;
    const int lrow = tid >> 3;
    const int lkk  = (tid & 7) << 3;
    uint32_t loff[4];
    #pragma unroll
    for (int it = 0; it < 4; it++) {
        uint32_t off = (uint32_t)(((lrow + it*32) << 7) + (lkk << 1));
        loff[it] = off ^ ((off >> 3) & 0x70u);
    }

    auto LOAD = [&](int c, int st) {
        const int k0 = c << 6;
        const uint32_t bs = bufu + st*65536;
        #pragma unroll
        for (int it = 0; it < 4; it++) {
            int row = lrow + it*32;
            size_t ga = (size_t)(m0 + row) * K + k0 + lkk;
            size_t gb = (size_t)(n0 + row) * K + k0 + lkk;
            cpa16(bs + loff[it],          Ahi + ga);
            cpa16(bs + 16384 + loff[it],  Alo + ga);
            cpa16(bs + 32768 + loff[it],  Bhi + gb);
            if (NP == 3)
                cpa16(bs + 49152 + loff[it], Blo + gb);
        }
        asm volatile("cp.async.commit_group;" ::: "memory");
    };

    LOAD(0, 0);

    for (int c = 0; c < nch; c++) {
        const int p = c & 1;
        if (c + 1 < nch) {
            LOAD(c + 1, 1 - p);
            asm volatile("cp.async.wait_group 1;" ::: "memory");
        } else {
            asm volatile("cp.async.wait_group 0;" ::: "memory");
        }
        __syncthreads();

        const uint32_t bA = bufu + p*65536;
        const uint32_t bB = bA + 32768;
        #pragma unroll
        for (int ks = 0; ks < 4; ks++) {
            const uint32_t koff = ((uint32_t)(ks*32 + lk)) ^ xorv;
            uint32_t bh[4][2], bl[4][2];
            #pragma unroll
            for (int bt = 0; bt < 2; bt++) {
                uint32_t r4[4];
                uint32_t baddr = bB + (uint32_t)((wn*32 + bt*16 + lr) << 7) + koff;
                ldsm4(r4, baddr);
                bh[bt*2][0]=r4[0]; bh[bt*2+1][0]=r4[1]; bh[bt*2][1]=r4[2]; bh[bt*2+1][1]=r4[3];
                if (NP == 3) {
                    ldsm4(r4, baddr + 16384);
                    bl[bt*2][0]=r4[0]; bl[bt*2+1][0]=r4[1]; bl[bt*2][1]=r4[2]; bl[bt*2+1][1]=r4[3];
                }
            }
            #pragma unroll
            for (int mt = 0; mt < 4; mt++) {
                uint32_t ah[4], al[4];
                uint32_t aaddr = bA + (uint32_t)((wm*64 + mt*16 + lr) << 7) + koff;
                ldsm4(ah, aaddr);
                ldsm4(al, aaddr + 16384);
                #pragma unroll
                for (int nt = 0; nt < 4; nt++) {
                    mma16816(acc[mt][nt], ah, bh[nt]);
                    if (NP == 3) mma16816(acc[mt][nt], ah, bl[nt]);
                    mma16816(acc[mt][nt], al, bh[nt]);
                }
            }
        }
        __syncthreads();
    }

    const int crow = lane >> 2;
    const int ccol = (lane & 3) << 1;
    if (glu) {
        const int half = Nc >> 1;
        #pragma unroll
        for (int mt = 0; mt < 4; mt++) {
            #pragma unroll
            for (int nt = 0; nt < 4; nt++) {
                int m  = m0 + wm*64 + mt*16 + crow;
                int n  = n0 + wn*32 + nt*8  + ccol;
                int oc = n >> 1;
                float a0 = acc[mt][nt][0], gt0 = acc[mt][nt][1];
                float a1 = acc[mt][nt][2], gt1 = acc[mt][nt][3];
                float r0 = a0 * gt0 / (1.0f + __expf(-gt0));
                float r1 = a1 * gt1 / (1.0f + __expf(-gt1));
                hlf h0 = __float2half_rn(r0);
                hlf h1 = __float2half_rn(r1);
                size_t o0 = (size_t)m*half + oc;
                size_t o1 = o0 + (size_t)8*half;
                Oh[o0] = h0; Ol[o0] = __float2half_rn(r0 - __half2float(h0));
                Oh[o1] = h1; Ol[o1] = __float2half_rn(r1 - __half2float(h1));
            }
        }
        return;
    }
    #pragma unroll
    for (int mt = 0; mt < 4; mt++) {
        #pragma unroll
        for (int nt = 0; nt < 4; nt++) {
            int m = m0 + wm*64 + mt*16 + crow;
            int n = n0 + wn*32 + nt*8  + ccol;
            size_t o0 = (size_t)m*Nc + n;
            size_t o1 = o0 + (size_t)8*Nc;
            float2 v0 = make_float2(acc[mt][nt][0], acc[mt][nt][1]);
            float2 v1 = make_float2(acc[mt][nt][2], acc[mt][nt][3]);
            if (addsrc) {
                float2 s0 = *(const float2*)(addsrc + o0);
                float2 s1 = *(const float2*)(addsrc + o1);
                v0.x += s0.x; v0.y += s0.y; v1.x += s1.x; v1.y += s1.y;
            }
            *(float2*)(C + o0) = v0;
            *(float2*)(C + o1) = v1;
        }
    }
}

// ---------------- merged q/k/v prep (verified by R15: rel_err unchanged) -------
#define QWARPS (BB*NN*HH)              // 32768
#define KVWARPS (BB*NKEY)              // 4100
__global__ __launch_bounds__(256) void prep_qkv_kernel(
    const float* __restrict__ qkv, const float* __restrict__ nullkv_l,
    float* __restrict__ q, float* __restrict__ kb, float* __restrict__ vb)
{
    int w = (blockIdx.x * blockDim.x + threadIdx.x) >> 5;
    int t = threadIdx.x & 31;
    if (w < QWARPS) {
        int h  = w & 7;
        int bi = w >> 3;
        int i  = bi & (NN - 1);
        const float* src = qkv + (size_t)bi*640 + h*DHH;
        float e0 = src[t], e1 = src[32+t];
        float ang = (float)i * c_invfreq[t >> 1];
        float c, sn;
        sincosf(ang, &sn, &c);
        float partner = __shfl_xor_sync(0xffffffffu, e0, 1);
        e0 = (t & 1) ? (e0*c + partner*sn) : (e0*c - partner*sn);
        float ss = e0*e0 + e1*e1;
        #pragma unroll
        for (int o = 16; o; o >>= 1) ss += __shfl_xor_sync(0xffffffffu, ss, o);
        float scale = 4.0f / fmaxf(sqrtf(ss), 1e-12f);
        float* dst = q + (size_t)bi*DD + h*DHH;
        dst[t]    = e0 * scale;
        dst[32+t] = e1 * scale;
    } else if (w < QWARPS + KVWARPS) {
        int w2 = w - QWARPS;
        int b = w2 / NKEY;
        int i = w2 - b*NKEY;
        float k0, k1, v0, v1;
        if (i == 0) {
            k0 = nullkv_l[t];    k1 = nullkv_l[32+t];
            v0 = nullkv_l[64+t]; v1 = nullkv_l[96+t];
        } else {
            const float* rp = qkv + ((size_t)b*NN + (i-1))*640 + 512;
            k0 = rp[t]; k1 = rp[32+t]; v0 = rp[64+t]; v1 = rp[96+t];
            float ang = (float)(i-1) * c_invfreq[t >> 1];
            float c, sn;
            sincosf(ang, &sn, &c);
            float partner = __shfl_xor_sync(0xffffffffu, k0, 1);
            k0 = (t & 1) ? (k0*c + partner*sn) : (k0*c - partner*sn);
        }
        float ss = k0*k0 + k1*k1;
        #pragma unroll
        for (int o = 16; o; o >>= 1) ss += __shfl_xor_sync(0xffffffffu, ss, o);
        float scale = 4.0f / fmaxf(sqrtf(ss), 1e-12f);
        size_t off = ((size_t)b*NKEY + i)*DHH;
        kb[off+t]    = k0 * scale;
        kb[off+32+t] = k1 * scale;
        vb[off+t]    = v0;
        vb[off+32+t] = v1;
    }
}

// ---------------- attention (R13 QS=8 design; longest blocks first) -----------
// Block = (b, 8-query strip), 8 warps = 8 heads. smem (floats):
//   qsT[h][d][qi] 4096 | kT[d][j65] 4160 | vs[j][d] 4096 | psT[h][qi][j] 4096
#define ATT_SMEM ((4096 + 64*65 + 4096 + 4096) * 4)

__global__ __launch_bounds__(256) void attn_kernel(
    const float* __restrict__ qn, const float* __restrict__ kb,
    const float* __restrict__ vb, const float* __restrict__ bias,
    hlf* __restrict__ oh, hlf* __restrict__ ol)
{
    float* qsT = (float*)dsm;            // 4096
    float* kT  = qsT + 4096;             // 64*65
    float* vs  = kT + 64*65;             // 4096
    float* psT = vs + 4096;              // 4096

    const int b   = blockIdx.y;
    const int i0  = (gridDim.x - 1 - blockIdx.x) * 8;   // longest causal blocks first
    const int tid = threadIdx.x;
    const int h   = tid >> 5;
    const int t   = tid & 31;

    for (int idx = tid; idx < 4096; idx += 256) {
        int d = idx & 63, qi = (idx >> 6) & 7, hh = idx >> 9;
        qsT[hh*512 + d*8 + qi] = qn[((size_t)b*NN + i0 + qi)*DD + hh*64 + d];
    }

    float lsum[8], acc0[8], acc1[8];
    #pragma unroll
    for (int qi = 0; qi < 8; qi++) { lsum[qi] = 0.f; acc0[qi] = 0.f; acc1[qi] = 0.f; }

    const float* qrow = qsT + h*512;
    float*       pw   = psT + h*512;
    const float* brow = bias + h*NKEY;

    int nkeys  = i0 + 10; if (nkeys > NKEY) nkeys = NKEY;
    int ntiles = (nkeys + 63) >> 6;

    __syncthreads();

    for (int jt = 0; jt < ntiles; jt++) {
        const int jbase = jt << 6;
        for (int idx = tid; idx < 4096; idx += 256) {
            int r = idx >> 6, c = idx & 63;
            int j = jbase + r;
            float kk = 0.f, vv = 0.f;
            if (j < NKEY) {
                size_t so = ((size_t)b*NKEY + j)*DHH + c;
                kk = kb[so]; vv = vb[so];
            }
            kT[c*65 + r] = kk;
            vs[r*64 + c] = vv;
        }
        __syncthreads();

        float s1[8], s2[8];
        #pragma unroll
        for (int qi = 0; qi < 8; qi++) { s1[qi] = 0.f; s2[qi] = 0.f; }
        #pragma unroll 4
        for (int d = 0; d < 64; d++) {
            float ka = kT[d*65 + t];
            float kc = kT[d*65 + 32 + t];
            float4 qa = *(const float4*)(qrow + d*8);
            float4 qb = *(const float4*)(qrow + d*8 + 4);
            s1[0] = fmaf(qa.x, ka, s1[0]); s2[0] = fmaf(qa.x, kc, s2[0]);
            s1[1] = fmaf(qa.y, ka, s1[1]); s2[1] = fmaf(qa.y, kc, s2[1]);
            s1[2] = fmaf(qa.z, ka, s1[2]); s2[2] = fmaf(qa.z, kc, s2[2]);
            s1[3] = fmaf(qa.w, ka, s1[3]); s2[3] = fmaf(qa.w, kc, s2[3]);
            s1[4] = fmaf(qb.x, ka, s1[4]); s2[4] = fmaf(qb.x, kc, s2[4]);
            s1[5] = fmaf(qb.y, ka, s1[5]); s2[5] = fmaf(qb.y, kc, s2[5]);
            s1[6] = fmaf(qb.z, ka, s1[6]); s2[6] = fmaf(qb.z, kc, s2[6]);
            s1[7] = fmaf(qb.w, ka, s1[7]); s2[7] = fmaf(qb.w, kc, s2[7]);
        }

        const int j1 = jbase + t, j2 = jbase + 32 + t;
        #pragma unroll
        for (int qi = 0; qi < 8; qi++) {
            int i = i0 + qi;
            float e1 = 0.f, e2 = 0.f;
            if (j1 <= i + 1 && j1 < NKEY) {
                int d = i - j1; d = d < 0 ? 0 : d;
                e1 = __expf(s1[qi] + __ldg(brow + d) - 16.5f);
            }
            if (j2 <= i + 1 && j2 < NKEY) {
                int d = i - j2; d = d < 0 ? 0 : d;
                e2 = __expf(s2[qi] + __ldg(brow + d) - 16.5f);
            }
            lsum[qi] += e1 + e2;
            pw[qi*64 + t]      = e1;
            pw[qi*64 + 32 + t] = e2;
        }
        __syncwarp();

        int jmax = nkeys - jbase; if (jmax > 64) jmax = 64;
        for (int j = 0; j < jmax; j++) {
            float v0 = vs[j*64 + t];
            float v1 = vs[j*64 + 32 + t];
            #pragma unroll
            for (int qi = 0; qi < 8; qi++) {
                float pj = pw[qi*64 + j];
                acc0[qi] = fmaf(pj, v0, acc0[qi]);
                acc1[qi] = fmaf(pj, v1, acc1[qi]);
            }
        }
        __syncthreads();
    }

    #pragma unroll
    for (int qi = 0; qi < 8; qi++) {
        float s = lsum[qi];
        #pragma unroll
        for (int off = 16; off; off >>= 1) s += __shfl_xor_sync(0xffffffffu, s, off);
        float inv = 1.0f / s;
        float v0 = acc0[qi] * inv;
        float v1 = acc1[qi] * inv;
        size_t off2 = ((size_t)b*NN + i0 + qi)*DD + h*DHH;
        hlf h0 = __float2half_rn(v0);
        hlf h1 = __float2half_rn(v1);
        oh[off2 + t]      = h0;
        oh[off2 + 32 + t] = h1;
        ol[off2 + t]      = __float2half_rn(v0 - __half2float(h0));
        ol[off2 + 32 + t] = __float2half_rn(v1 - __half2float(h1));
    }
}

// ---------------- host ----------------
extern "C" void kernel_launch(void* const* d_in, const int* in_sizes, int n_in,
                              void* d_out, int out_size)
{
    const float* x         = (const float*)d_in[0];
    const float* emb       = (const float*)d_in[1];
    const float* g_attn    = (const float*)d_in[2];
    const float* null_kv   = (const float*)d_in[3];
    const float* Wq        = (const float*)d_in[4];
    const float* Wkv       = (const float*)d_in[5];
    const float* Wo        = (const float*)d_in[6];
    const float* g_attn_o  = (const float*)d_in[7];
    const float* g_ff_     = (const float*)d_in[8];
    const float* W1        = (const float*)d_in[9];
    const float* W2        = (const float*)d_in[10];
    const float* g_final   = (const float*)d_in[11];
    const float* Wproj     = (const float*)d_in[12];
    float* out = (float*)d_out;

    void *p;
    cudaGetSymbolAddress(&p, g_x);    float* xb  = (float*)p;
    cudaGetSymbolAddress(&p, g_qkv);  float* qkvb= (float*)p;
    cudaGetSymbolAddress(&p, g_q);    float* qb  = (float*)p;
    cudaGetSymbolAddress(&p, g_k);    float* kbb = (float*)p;
    cudaGetSymbolAddress(&p, g_v);    float* vbb = (float*)p;
    cudaGetSymbolAddress(&p, g_pr);   float* prb = (float*)p;
    cudaGetSymbolAddress(&p, g_bias); float* bib = (float*)p;
    cudaGetSymbolAddress(&p, g_xnh);  hlf* xnh = (hlf*)p;
    cudaGetSymbolAddress(&p, g_xnl);  hlf* xnl = (hlf*)p;
    cudaGetSymbolAddress(&p, g_aoh);  hlf* aoh = (hlf*)p;
    cudaGetSymbolAddress(&p, g_aol);  hlf* aol = (hlf*)p;
    cudaGetSymbolAddress(&p, g_ffh);  hlf* ffh = (hlf*)p;
    cudaGetSymbolAddress(&p, g_ffl);  hlf* ffl = (hlf*)p;
    cudaGetSymbolAddress(&p, g_wqkvh);hlf* wqkvh=(hlf*)p;
    cudaGetSymbolAddress(&p, g_wqkvl);hlf* wqkvl=(hlf*)p;
    cudaGetSymbolAddress(&p, g_woh);  hlf* woh = (hlf*)p;
    cudaGetSymbolAddress(&p, g_w1h);  hlf* w1h = (hlf*)p;
    cudaGetSymbolAddress(&p, g_w2h);  hlf* w2h = (hlf*)p;
    cudaGetSymbolAddress(&p, g_wph);  hlf* wph = (hlf*)p;

    cudaFuncSetAttribute(tc_gemm_t<2>, cudaFuncAttributeMaxDynamicSharedMemorySize, TCG_SMEM);
    cudaFuncSetAttribute(tc_gemm_t<3>, cudaFuncAttributeMaxDynamicSharedMemorySize, TCG_SMEM);
    cudaFuncSetAttribute(attn_kernel, cudaFuncAttributeMaxDynamicSharedMemorySize, ATT_SMEM);

    const int M = BB * NN;           // 4096
    dim3 wb(32, 8);

    copy_kernel<<<(M*DD + 255)/256, 256>>>(x, xb, M*DD);
    bias_kernel<<<(NKEY + 255)/256, 256>>>(emb, bib);

    // weight transforms (fp32 [K][Nc] -> fp16 [n'][K]; qkv also lo)
    wsplit_kernel<<<dim3(16, 16, LL), wb>>>(Wq,   wqkvh, wqkvl, DD, DD,  (size_t)640*DD, 0,              0);
    wsplit_kernel<<<dim3(4,  16, LL), wb>>>(Wkv,  wqkvh, wqkvl, DD, 128, (size_t)640*DD, (size_t)512*DD, 0);
    wsplit_kernel<<<dim3(16, 16, LL), wb>>>(Wo,   woh,  nullptr, DD, DD,   (size_t)DD*DD, 0, 0);
    wsplit_kernel<<<dim3(128,16, LL), wb>>>(W1,   w1h,  nullptr, DD, 4096, (size_t)4096*DD, 0, 1);  // a/gate interleave
    wsplit_kernel<<<dim3(16, 64, LL), wb>>>(W2,   w2h,  nullptr, FFI, DD,  (size_t)DD*FFI, 0, 0);
    wsplit_kernel<<<dim3(16, 16, 1),  wb>>>(Wproj,wph,  nullptr, DD, DD,   0, 0, 0);

    const int prep_blocks = (QWARPS + KVWARPS + 7) / 8;

    for (int l = 0; l < LL; l++) {
        // attention block
        ln_kernel<<<M, 128>>>(xb, g_attn + l*DD, nullptr, nullptr, xnh, xnl, 0);
        tc_gemm_t<3><<<dim3(5, 32), 256, TCG_SMEM>>>(xnh, xnl,
            wqkvh + (size_t)l*640*DD, wqkvl + (size_t)l*640*DD,
            qkvb, nullptr, nullptr, nullptr, DD, 640, 0);
        prep_qkv_kernel<<<prep_blocks, 256>>>(qkvb, null_kv + l*2*DHH, qb, kbb, vbb);
        attn_kernel<<<dim3(NN/8, BB), 256, ATT_SMEM>>>(qb, kbb, vbb, bib, aoh, aol);
        tc_gemm_t<2><<<dim3(4, 32), 256, TCG_SMEM>>>(aoh, aol,
            woh + (size_t)l*DD*DD, nullptr,
            prb, nullptr, nullptr, nullptr, DD, DD, 0);
        // x += LN(o@Wo); xn = LN(x) for FF  (fused)
        ln_add_ln_kernel<<<M, 128>>>(prb, g_attn_o + l*DD, g_ff_ + l*DD, xb, xnh, xnl);
        // feed-forward block: W1 with fused GLU epilogue -> ffh/ffl
        tc_gemm_t<2><<<dim3(32, 32), 256, TCG_SMEM>>>(xnh, xnl,
            w1h + (size_t)l*4096*DD, nullptr,
            nullptr, nullptr, ffh, ffl, DD, 4096, 1);
        tc_gemm_t<2><<<dim3(4, 32), 256, TCG_SMEM>>>(ffh, ffl,
            w2h + (size_t)l*DD*FFI, nullptr,
            xb, xb, nullptr, nullptr, FFI, DD, 0);
    }
    ln_kernel<<<M, 128>>>(xb, g_final, nullptr, nullptr, xnh, xnl, 1);   // stable LN
    tc_gemm_t<2><<<dim3(4, 32), 256, TCG_SMEM>>>(xnh, xnl, wph, nullptr, out, nullptr,
                                                 nullptr, nullptr, DD, DD, 0);
}